// round 13
// baseline (speedup 1.0000x reference)
#include <cuda_runtime.h>
#include <cstdint>

// Problem constants (B=256, M=N=512 fixed by the dataset).
#define BDIM   512
#define CL     8          // CTAs per cluster (one cluster per batch element)
#define RPC    64         // rows per CTA (8 * 64 = 512 = M)
#define NCOL   512
#define MROWS  512
#define PAD    520        // row pitch in floats: 520 mod 32 = 8 -> conflict-free both phases
#define MAXIT  20
#define EPSF   1e-10f

#define SMEM_FLOATS (RPC*PAD + NCOL + RPC + CL*64)
#define SMEM_BYTES  (SMEM_FLOATS * 4)

__device__ __forceinline__ uint32_t smem_u32(const void* p) {
    uint32_t a;
    asm("{ .reg .u64 t; cvta.to.shared.u64 t, %1; cvt.u32.u64 %0, t; }"
        : "=r"(a) : "l"(p));
    return a;
}
__device__ __forceinline__ uint32_t mapa_u32(uint32_t a, uint32_t rank) {
    uint32_t r;
    asm("mapa.shared::cluster.u32 %0, %1, %2;" : "=r"(r) : "r"(a), "r"(rank));
    return r;
}
__device__ __forceinline__ void st_cluster_f32(uint32_t a, float v) {
    asm volatile("st.shared::cluster.f32 [%0], %1;" :: "r"(a), "f"(v) : "memory");
}
__device__ __forceinline__ uint32_t cta_rank() {
    uint32_t r;
    asm("mov.u32 %0, %%cluster_ctarank;" : "=r"(r));
    return r;
}
__device__ __forceinline__ void cluster_sync() {
    asm volatile("barrier.cluster.arrive.aligned;" ::: "memory");
    asm volatile("barrier.cluster.wait.aligned;"   ::: "memory");
}

__global__ void __launch_bounds__(BDIM, 1) __cluster_dims__(CL, 1, 1)
sinkhorn_cluster_kernel(const float* __restrict__ S,
                        const int*   __restrict__ nrows,
                        const int*   __restrict__ ncols,
                        float*       __restrict__ out)
{
    extern __shared__ float sm[];
    float* tile = sm;                    // [RPC][PAD]  A+eps, local row slice
    float* cv   = tile + RPC * PAD;      // [NCOL]      column factors (replicated per CTA)
    float* rv   = cv + NCOL;             // [RPC]       row factors for local rows
    float* recv = rv + RPC;              // [CL][64]    partial col sums from each CTA

    const int      t     = threadIdx.x;
    const uint32_t rank  = cta_rank();          // 0..7
    const int      batch = blockIdx.x / CL;
    const int      row0  = (int)rank * RPC;
    const int      nr    = nrows[batch];
    const int      nc    = ncols[batch];

    // ---- load local 64x512 slice (+eps) into padded SMEM ----
    const float4* A4 = (const float4*)(S + (size_t)batch * MROWS * NCOL
                                         + (size_t)row0 * NCOL);
    #pragma unroll
    for (int i = t; i < RPC * (NCOL / 4); i += BDIM) {
        int r  = i >> 7;          // / (NCOL/4)
        int c4 = i & 127;
        float4 v = A4[r * (NCOL / 4) + c4];
        v.x += EPSF; v.y += EPSF; v.z += EPSF; v.w += EPSF;
        *(float4*)(tile + r * PAD + (c4 << 2)) = v;
    }
    // r_i = 1 for valid rows, 0 for invalid -> col sums need no explicit mask
    if (t < RPC) rv[t] = (row0 + t < nr) ? 1.0f : 0.0f;
    __syncthreads();

    const uint32_t recv_u32 = smem_u32(recv);
    const uint32_t cv_u32   = smem_u32(cv);

    for (int it = 0; it < MAXIT; ++it) {
        if ((it & 1) == 0) {
            // ---------- column phase: c_j = 1 / sum_i A_ij r_i ----------
            const int j = t;                      // one thread per column
            float u = 0.0f;
            #pragma unroll 8
            for (int r = 0; r < RPC; ++r)
                u = fmaf(tile[r * PAD + j], rv[r], u);

            // push partial to owning CTA (owner = j/64) at recv[rank][j%64]
            uint32_t owner = (uint32_t)(j >> 6);
            uint32_t dst = mapa_u32(recv_u32, owner)
                         + (uint32_t)(((int)rank << 6) + (j & 63)) * 4u;
            st_cluster_f32(dst, u);
            cluster_sync();

            // owner totals its 64 columns, computes c, broadcasts to all CTAs
            if (t < 64) {
                float tot = 0.0f;
                #pragma unroll
                for (int k = 0; k < CL; ++k) tot += recv[(k << 6) + t];
                int   jg   = ((int)rank << 6) + t;
                float cval = (jg < nc) ? (1.0f / tot) : 0.0f;  // c=0 outside block
                #pragma unroll
                for (int k = 0; k < CL; ++k) {
                    uint32_t cdst = mapa_u32(cv_u32, (uint32_t)k)
                                  + (uint32_t)jg * 4u;
                    st_cluster_f32(cdst, cval);
                }
            }
            cluster_sync();
        } else {
            // ---------- row phase (CTA-local): r_i = 1 / sum_j A_ij c_j ----------
            const int row = t >> 3;               // 8 threads per row
            const int q   = t & 7;
            const float* trow = tile + row * PAD;
            float v = 0.0f;
            #pragma unroll 16
            for (int k = 0; k < 64; ++k) {
                int j = q + (k << 3);              // stride-8 columns: conflict-free
                v = fmaf(trow[j], cv[j], v);
            }
            v += __shfl_down_sync(0xffffffffu, v, 4, 8);
            v += __shfl_down_sync(0xffffffffu, v, 2, 8);
            v += __shfl_down_sync(0xffffffffu, v, 1, 8);
            if (q == 0)
                rv[row] = (row0 + row < nr) ? (1.0f / v) : 0.0f;
            __syncthreads();
        }
    }

    // ---- final: out_ij = (A_ij+eps) * r_i * c_j (zeros outside block via r/c=0) ----
    float4* O4 = (float4*)(out + (size_t)batch * MROWS * NCOL
                               + (size_t)row0 * NCOL);
    #pragma unroll
    for (int i = t; i < RPC * (NCOL / 4); i += BDIM) {
        int r  = i >> 7;
        int c4 = i & 127;
        int j  = c4 << 2;
        float  rr = rv[r];
        float4 a  = *(const float4*)(tile + r * PAD + j);
        float4 c  = *(const float4*)(cv + j);
        float4 v;
        v.x = a.x * rr * c.x;
        v.y = a.y * rr * c.y;
        v.z = a.z * rr * c.z;
        v.w = a.w * rr * c.w;
        O4[r * (NCOL / 4) + c4] = v;
    }
}

extern "C" void kernel_launch(void* const* d_in, const int* in_sizes, int n_in,
                              void* d_out, int out_size)
{
    const float* s  = (const float*)d_in[0];
    const int* nrw  = (const int*)d_in[1];
    const int* ncl  = (const int*)d_in[2];
    float* out      = (float*)d_out;

    const int B = in_sizes[1];   // nrows element count = batch size

    // 137,472 B dynamic SMEM per CTA (within 227 KB limit). Not a stream op;
    // safe under graph capture and idempotent.
    cudaFuncSetAttribute(sinkhorn_cluster_kernel,
                         cudaFuncAttributeMaxDynamicSharedMemorySize, SMEM_BYTES);

    sinkhorn_cluster_kernel<<<B * CL, BDIM, SMEM_BYTES>>>(s, nrw, ncl, out);
}